// round 1
// baseline (speedup 1.0000x reference)
#include <cuda_runtime.h>

// ---------------- problem constants (fixed shapes per reference) ------------
#define NN 100000
#define NG 1024

// ---------------- scratch (static device globals; no allocs allowed) -------
__device__ float g_degf[NN];
__device__ float g_dinv[NN];
__device__ __align__(16) float4 g_agg1[NN * 4];   // 16 f32 per node
__device__ __align__(16) float4 g_t2  [NN * 8];   // 32 f32 per node (h1 @ W2)
__device__ __align__(16) float4 g_agg2[NN * 8];   // 32 f32 per node
__device__ __align__(16) float4 g_gsum[NG * 8];   // 32 f32 per graph
__device__ float g_gcnt[NG];

// no-return vector f32 atomic add (sm_90+): one REDG.128 instead of 4 RED.32
__device__ __forceinline__ void red_add_v4(float4* p, float4 v) {
    asm volatile("red.global.add.v4.f32 [%0], {%1, %2, %3, %4};"
                 :: "l"(p), "f"(v.x), "f"(v.y), "f"(v.z), "f"(v.w)
                 : "memory");
}

// ---------------- kernels ---------------------------------------------------

__global__ void k_init(int n) {
    int t = blockIdx.x * blockDim.x + threadIdx.x;
    const float4 z = make_float4(0.f, 0.f, 0.f, 0.f);
    if (t < n * 8) g_agg2[t] = z;
    if (t < n * 4) g_agg1[t] = z;
    if (t < n)     g_degf[t] = 1.0f;       // self-loop contributes 1 to degree
    if (t < NG * 8) g_gsum[t] = z;
    if (t < NG)     g_gcnt[t] = 0.f;
}

__global__ void k_deg(const int* __restrict__ dst, int E) {
    int e = blockIdx.x * blockDim.x + threadIdx.x;
    if (e < E) atomicAdd(&g_degf[dst[e]], 1.0f);
}

__global__ void k_dinv(int n) {
    int i = blockIdx.x * blockDim.x + threadIdx.x;
    if (i < n) g_dinv[i] = rsqrtf(g_degf[i]);   // deg >= 1 always (self-loop)
}

// Layer-1 edge aggregation in 16-dim input space (linearity of GCN):
// agg1[d] += x[s] * dinv[s]*dinv[d]
__global__ void k_scatter1(const int* __restrict__ src, const int* __restrict__ dst,
                           const float4* __restrict__ x4, int E) {
    int e = blockIdx.x * blockDim.x + threadIdx.x;
    if (e >= E) return;
    int s = src[e], d = dst[e];
    float w = g_dinv[s] * g_dinv[d];
    const float4* xs = x4 + (size_t)s * 4;
    float4* ad = g_agg1 + (size_t)d * 4;
    #pragma unroll
    for (int j = 0; j < 4; j++) {
        float4 v = __ldg(xs + j);
        red_add_v4(ad + j, make_float4(v.x * w, v.y * w, v.z * w, v.w * w));
    }
}

// Per node: a16 = agg1 + x*dinv^2 (self loop); h64 = relu(a16@W1 + b1);
// t32 = h64 @ W2  (pre-multiply layer-2 weights before edge scatter)
__global__ void k_node1(const float4* __restrict__ x4,
                        const float* __restrict__ W1, const float* __restrict__ b1,
                        const float* __restrict__ W2, int n) {
    __shared__ float sW1[16 * 64];
    __shared__ float sb1[64];
    __shared__ float sW2[64 * 32];
    for (int t = threadIdx.x; t < 16 * 64; t += blockDim.x) sW1[t] = W1[t];
    for (int t = threadIdx.x; t < 64;      t += blockDim.x) sb1[t] = b1[t];
    for (int t = threadIdx.x; t < 64 * 32; t += blockDim.x) sW2[t] = W2[t];
    __syncthreads();

    int i = blockIdx.x * blockDim.x + threadIdx.x;
    if (i >= n) return;

    float w = g_dinv[i];
    float sw = w * w;
    float a[16];
    #pragma unroll
    for (int j = 0; j < 4; j++) {
        float4 ag = g_agg1[(size_t)i * 4 + j];
        float4 xv = __ldg(x4 + (size_t)i * 4 + j);
        a[4 * j + 0] = ag.x + xv.x * sw;
        a[4 * j + 1] = ag.y + xv.y * sw;
        a[4 * j + 2] = ag.z + xv.z * sw;
        a[4 * j + 3] = ag.w + xv.w * sw;
    }

    float t[32];
    #pragma unroll
    for (int k = 0; k < 32; k++) t[k] = 0.f;

    #pragma unroll 4
    for (int j = 0; j < 64; j++) {
        float h = sb1[j];
        #pragma unroll
        for (int f = 0; f < 16; f++) h += a[f] * sW1[f * 64 + j];
        h = fmaxf(h, 0.f);
        #pragma unroll
        for (int k = 0; k < 32; k++) t[k] += h * sW2[j * 32 + k];
    }

    float4* o = g_t2 + (size_t)i * 8;
    #pragma unroll
    for (int j = 0; j < 8; j++)
        o[j] = make_float4(t[4 * j], t[4 * j + 1], t[4 * j + 2], t[4 * j + 3]);
}

// Layer-2 edge aggregation in 32-dim output space:
// agg2[d] += t2[s] * dinv[s]*dinv[d]
__global__ void k_scatter2(const int* __restrict__ src, const int* __restrict__ dst, int E) {
    int e = blockIdx.x * blockDim.x + threadIdx.x;
    if (e >= E) return;
    int s = src[e], d = dst[e];
    float w = g_dinv[s] * g_dinv[d];
    const float4* ts = g_t2 + (size_t)s * 8;
    float4* ad = g_agg2 + (size_t)d * 8;
    #pragma unroll
    for (int j = 0; j < 8; j++) {
        float4 v = __ldg(ts + j);
        red_add_v4(ad + j, make_float4(v.x * w, v.y * w, v.z * w, v.w * w));
    }
}

// h2 = relu(agg2 + t2*dinv^2 + b2); accumulate into per-graph sums + counts
__global__ void k_node2pool(const int* __restrict__ batch,
                            const float* __restrict__ b2, int n) {
    int i = blockIdx.x * blockDim.x + threadIdx.x;
    if (i >= n) return;
    float w = g_dinv[i];
    float sw = w * w;
    int b = batch[i];
    float4* gs = g_gsum + (size_t)b * 8;
    #pragma unroll
    for (int j = 0; j < 8; j++) {
        float4 ag = g_agg2[(size_t)i * 8 + j];
        float4 tv = g_t2[(size_t)i * 8 + j];
        float4 v;
        v.x = fmaxf(ag.x + tv.x * sw + __ldg(b2 + 4 * j + 0), 0.f);
        v.y = fmaxf(ag.y + tv.y * sw + __ldg(b2 + 4 * j + 1), 0.f);
        v.z = fmaxf(ag.z + tv.z * sw + __ldg(b2 + 4 * j + 2), 0.f);
        v.w = fmaxf(ag.w + tv.w * sw + __ldg(b2 + 4 * j + 3), 0.f);
        red_add_v4(gs + j, v);
    }
    atomicAdd(&g_gcnt[b], 1.0f);
}

// Per-graph MLP head: mean -> 32x16 relu -> 16x1 sigmoid
__global__ void k_mlp(const float* __restrict__ fc1W, const float* __restrict__ fc1b,
                      const float* __restrict__ fc2W, const float* __restrict__ fc2b,
                      float* __restrict__ out) {
    int t = blockIdx.x * blockDim.x + threadIdx.x;
    if (t >= NG) return;
    float inv = 1.0f / fmaxf(g_gcnt[t], 1.0f);
    float g[32];
    #pragma unroll
    for (int j = 0; j < 8; j++) {
        float4 v = g_gsum[(size_t)t * 8 + j];
        g[4 * j + 0] = v.x * inv;
        g[4 * j + 1] = v.y * inv;
        g[4 * j + 2] = v.z * inv;
        g[4 * j + 3] = v.w * inv;
    }
    float r[16];
    #pragma unroll
    for (int j = 0; j < 16; j++) {
        float s = __ldg(fc1b + j);
        #pragma unroll
        for (int i = 0; i < 32; i++) s += g[i] * __ldg(fc1W + i * 16 + j);
        r[j] = fmaxf(s, 0.f);
    }
    float s = __ldg(fc2b);
    #pragma unroll
    for (int j = 0; j < 16; j++) s += r[j] * __ldg(fc2W + j);
    out[t] = 1.0f / (1.0f + expf(-s));
}

// ---------------- launch -----------------------------------------------------

extern "C" void kernel_launch(void* const* d_in, const int* in_sizes, int n_in,
                              void* d_out, int out_size) {
    const float* x     = (const float*)d_in[0];
    const int*   ei    = (const int*)  d_in[1];
    const int*   batch = (const int*)  d_in[2];
    const float* W1    = (const float*)d_in[3];
    const float* b1    = (const float*)d_in[4];
    const float* W2    = (const float*)d_in[5];
    const float* b2    = (const float*)d_in[6];
    const float* fc1W  = (const float*)d_in[7];
    const float* fc1b  = (const float*)d_in[8];
    const float* fc2W  = (const float*)d_in[9];
    const float* fc2b  = (const float*)d_in[10];
    float* out = (float*)d_out;

    int n = in_sizes[0] / 16;        // 100000
    int E = in_sizes[1] / 2;         // 3200000
    const int* src = ei;
    const int* dst = ei + E;

    const int B = 256;
    int initN = n * 8;               // largest init extent (agg2 float4 count)

    k_init    <<<(initN + B - 1) / B, B>>>(n);
    k_deg     <<<(E + B - 1) / B, B>>>(dst, E);
    k_dinv    <<<(n + B - 1) / B, B>>>(n);
    k_scatter1<<<(E + B - 1) / B, B>>>(src, dst, (const float4*)x, E);
    k_node1   <<<(n + B - 1) / B, B>>>((const float4*)x, W1, b1, W2, n);
    k_scatter2<<<(E + B - 1) / B, B>>>(src, dst, E);
    k_node2pool<<<(n + B - 1) / B, B>>>(batch, b2, n);
    k_mlp     <<<(NG + B - 1) / B, B>>>(fc1W, fc1b, fc2W, fc2b, out);
}

// round 4
// speedup vs baseline: 1.8259x; 1.8259x over previous
#include <cuda_runtime.h>
#include <cuda_fp16.h>
#include <cstdint>

// ---------------- problem constants ----------------
#define NN 100000
#define NE 3200000
#define NG 1024
#define SCAN_B 1024           // elements per scan block
#define MAXB 128              // max scan blocks (100000/1024 = 98)

// ---------------- scratch ----------------
__device__ int   g_degi[NN];                   // real in-degree (excl self)
__device__ int   g_rowstart[NN];
__device__ int   g_cursor[NN];
__device__ float g_dinv[NN];
__device__ int   g_blocksum[MAXB];
__device__ int   g_blockoff[MAXB];
__device__ int   g_col[NE];                    // CSR: src ids grouped by dst
__device__ __align__(16) __half g_xs [NN * 16];   // x * dinv  (fp16)
__device__ __align__(16) __half g_t2s[NN * 32];   // (h1@W2) * dinv (fp16)
__device__ __align__(16) float  g_agg1[NN * 16];
__device__ float g_gsum[NG * 32];
__device__ float g_gcnt[NG];

// ---------------- helpers ----------------
__device__ __forceinline__ unsigned int h2_bits(float a, float b) {
    __half2 h = __floats2half2_rn(a, b);
    return *reinterpret_cast<unsigned int*>(&h);
}

__device__ __forceinline__ void acc_u4(float* acc, uint4 a, int base) {
    const __half2* h = reinterpret_cast<const __half2*>(&a);
    #pragma unroll
    for (int j = 0; j < 4; j++) {
        float2 f = __half22float2(h[j]);
        acc[base + 2 * j]     += f.x;
        acc[base + 2 * j + 1] += f.y;
    }
}

// recursive-halving butterfly stage: after stages H=...,1 each lane holds one
// feature's warp-total (feature index = lane bits covered by the stages)
template <int H>
__device__ __forceinline__ void halve(float* acc, int lane) {
    bool up = (lane & H) != 0;
    #pragma unroll
    for (int i = 0; i < H; i++) {
        float lo = acc[i], hi = acc[i + H];
        float send = up ? lo : hi;
        float keep = up ? hi : lo;
        acc[i] = keep + __shfl_xor_sync(0xffffffffu, send, H);
    }
}

// ---------------- kernels ----------------
__global__ void k_init(int n) {
    int t = blockIdx.x * blockDim.x + threadIdx.x;
    if (t < n) g_degi[t] = 0;
    if (t < NG * 32) g_gsum[t] = 0.f;
    if (t < NG) g_gcnt[t] = 0.f;
}

__global__ void k_deg(const int* __restrict__ dst, int E) {
    int e = blockIdx.x * blockDim.x + threadIdx.x;
    if (e < E) atomicAdd(&g_degi[dst[e]], 1);
}

__global__ void k_scan1(int n) {           // grid = nb, block = SCAN_B
    __shared__ int s[SCAN_B];
    int t = threadIdx.x;
    int i = blockIdx.x * SCAN_B + t;
    int v = (i < n) ? g_degi[i] : 0;
    s[t] = v;
    __syncthreads();
    #pragma unroll
    for (int d = 1; d < SCAN_B; d <<= 1) {
        int add = (t >= d) ? s[t - d] : 0;
        __syncthreads();
        s[t] += add;
        __syncthreads();
    }
    if (i < n) g_rowstart[i] = s[t] - v;   // exclusive
    if (t == SCAN_B - 1) g_blocksum[blockIdx.x] = s[t];
}

__global__ void k_scan2(int nb) {          // 1 block, MAXB threads
    __shared__ int s[MAXB];
    int t = threadIdx.x;
    int v = (t < nb) ? g_blocksum[t] : 0;
    s[t] = v;
    __syncthreads();
    #pragma unroll
    for (int d = 1; d < MAXB; d <<= 1) {
        int add = (t >= d) ? s[t - d] : 0;
        __syncthreads();
        s[t] += add;
        __syncthreads();
    }
    g_blockoff[t] = s[t] - v;              // exclusive
}

// finalize offsets, cursors, dinv, and xs = x * dinv (fp16)
__global__ void k_scan3(const float4* __restrict__ x4, int n) {
    int i = blockIdx.x * blockDim.x + threadIdx.x;
    if (i >= n) return;
    int rs = g_rowstart[i] + g_blockoff[i >> 10];
    g_rowstart[i] = rs;
    g_cursor[i] = rs;
    float dv = rsqrtf((float)(g_degi[i] + 1));   // +1 self loop
    g_dinv[i] = dv;
    uint4* o = reinterpret_cast<uint4*>(g_xs + (size_t)i * 16);
    #pragma unroll
    for (int j = 0; j < 2; j++) {
        float4 a = __ldg(x4 + (size_t)i * 4 + 2 * j);
        float4 b = __ldg(x4 + (size_t)i * 4 + 2 * j + 1);
        uint4 u;
        u.x = h2_bits(a.x * dv, a.y * dv);
        u.y = h2_bits(a.z * dv, a.w * dv);
        u.z = h2_bits(b.x * dv, b.y * dv);
        u.w = h2_bits(b.z * dv, b.w * dv);
        o[j] = u;
    }
}

__global__ void k_fill(const int* __restrict__ src, const int* __restrict__ dst, int E) {
    int e = blockIdx.x * blockDim.x + threadIdx.x;
    if (e >= E) return;
    int pos = atomicAdd(&g_cursor[dst[e]], 1);
    g_col[pos] = src[e];
}

// Layer-1 aggregation (gather, warp per node): a16[d] = dinv_d * (Σ xs[src] + xs[d])
__global__ void k_gather1(int n) {
    int w = (blockIdx.x * blockDim.x + threadIdx.x) >> 5;
    int lane = threadIdx.x & 31;
    if (w >= n) return;
    int rs = g_rowstart[w], dg = g_degi[w];
    float acc[16];
    #pragma unroll
    for (int i = 0; i < 16; i++) acc[i] = 0.f;
    for (int k = lane; k < dg + 1; k += 32) {     // extra slot = self loop
        int c = (k < dg) ? g_col[rs + k] : w;
        const uint4* p = reinterpret_cast<const uint4*>(g_xs + (size_t)c * 16);
        acc_u4(acc, __ldg(p), 0);
        acc_u4(acc, __ldg(p + 1), 8);
    }
    #pragma unroll
    for (int i = 0; i < 16; i++) acc[i] += __shfl_xor_sync(0xffffffffu, acc[i], 16);
    halve<8>(acc, lane); halve<4>(acc, lane); halve<2>(acc, lane); halve<1>(acc, lane);
    if (lane < 16) g_agg1[(size_t)w * 16 + lane] = acc[0] * g_dinv[w];
}

// Per node: h64 = relu(a16@W1+b1); t2s = (h64@W2)*dinv (fp16)
__global__ void k_node1(const float* __restrict__ W1, const float* __restrict__ b1,
                        const float* __restrict__ W2, int n) {
    __shared__ float sW1[16 * 64];
    __shared__ float sb1[64];
    __shared__ float sW2[64 * 32];
    for (int t = threadIdx.x; t < 16 * 64; t += blockDim.x) sW1[t] = W1[t];
    for (int t = threadIdx.x; t < 64;      t += blockDim.x) sb1[t] = b1[t];
    for (int t = threadIdx.x; t < 64 * 32; t += blockDim.x) sW2[t] = W2[t];
    __syncthreads();

    int i = blockIdx.x * blockDim.x + threadIdx.x;
    if (i >= n) return;

    float a[16];
    const float4* av = reinterpret_cast<const float4*>(g_agg1 + (size_t)i * 16);
    #pragma unroll
    for (int j = 0; j < 4; j++) {
        float4 v = av[j];
        a[4 * j] = v.x; a[4 * j + 1] = v.y; a[4 * j + 2] = v.z; a[4 * j + 3] = v.w;
    }

    float t[32];
    #pragma unroll
    for (int k = 0; k < 32; k++) t[k] = 0.f;
    #pragma unroll 4
    for (int j = 0; j < 64; j++) {
        float h = sb1[j];
        #pragma unroll
        for (int f = 0; f < 16; f++) h += a[f] * sW1[f * 64 + j];
        h = fmaxf(h, 0.f);
        #pragma unroll
        for (int k = 0; k < 32; k++) t[k] += h * sW2[j * 32 + k];
    }

    float dv = g_dinv[i];
    uint4* o = reinterpret_cast<uint4*>(g_t2s + (size_t)i * 32);
    #pragma unroll
    for (int j = 0; j < 4; j++) {
        uint4 u;
        u.x = h2_bits(t[8 * j]     * dv, t[8 * j + 1] * dv);
        u.y = h2_bits(t[8 * j + 2] * dv, t[8 * j + 3] * dv);
        u.z = h2_bits(t[8 * j + 4] * dv, t[8 * j + 5] * dv);
        u.w = h2_bits(t[8 * j + 6] * dv, t[8 * j + 7] * dv);
        o[j] = u;
    }
}

// Layer-2 aggregation (gather, warp per node) fused with relu + mean-pool accumulate.
// After reduction lane L holds feature L's total.
__global__ void k_gather2(const int* __restrict__ batch, const float* __restrict__ b2, int n) {
    int w = (blockIdx.x * blockDim.x + threadIdx.x) >> 5;
    int lane = threadIdx.x & 31;
    if (w >= n) return;
    int rs = g_rowstart[w], dg = g_degi[w];
    float acc[32];
    #pragma unroll
    for (int i = 0; i < 32; i++) acc[i] = 0.f;
    for (int k = lane; k < dg + 1; k += 32) {     // extra slot = self loop
        int c = (k < dg) ? g_col[rs + k] : w;
        const uint4* p = reinterpret_cast<const uint4*>(g_t2s + (size_t)c * 32);
        acc_u4(acc, __ldg(p),     0);
        acc_u4(acc, __ldg(p + 1), 8);
        acc_u4(acc, __ldg(p + 2), 16);
        acc_u4(acc, __ldg(p + 3), 24);
    }
    halve<16>(acc, lane); halve<8>(acc, lane); halve<4>(acc, lane);
    halve<2>(acc, lane);  halve<1>(acc, lane);
    // lane L holds feature L
    float h2 = fmaxf(acc[0] * g_dinv[w] + __ldg(b2 + lane), 0.f);
    int b = batch[w];
    atomicAdd(&g_gsum[(size_t)b * 32 + lane], h2);
    if (lane == 0) atomicAdd(&g_gcnt[b], 1.0f);
}

// Per-graph head: mean -> 32x16 relu -> 16x1 sigmoid
__global__ void k_mlp(const float* __restrict__ fc1W, const float* __restrict__ fc1b,
                      const float* __restrict__ fc2W, const float* __restrict__ fc2b,
                      float* __restrict__ out) {
    int t = blockIdx.x * blockDim.x + threadIdx.x;
    if (t >= NG) return;
    float inv = 1.0f / fmaxf(g_gcnt[t], 1.0f);
    float g[32];
    #pragma unroll
    for (int j = 0; j < 32; j++) g[j] = g_gsum[(size_t)t * 32 + j] * inv;
    float r[16];
    #pragma unroll
    for (int j = 0; j < 16; j++) {
        float s = __ldg(fc1b + j);
        #pragma unroll
        for (int i = 0; i < 32; i++) s += g[i] * __ldg(fc1W + i * 16 + j);
        r[j] = fmaxf(s, 0.f);
    }
    float s = __ldg(fc2b);
    #pragma unroll
    for (int j = 0; j < 16; j++) s += r[j] * __ldg(fc2W + j);
    out[t] = 1.0f / (1.0f + expf(-s));
}

// ---------------- launch ----------------
extern "C" void kernel_launch(void* const* d_in, const int* in_sizes, int n_in,
                              void* d_out, int out_size) {
    const float* x     = (const float*)d_in[0];
    const int*   ei    = (const int*)  d_in[1];
    const int*   batch = (const int*)  d_in[2];
    const float* W1    = (const float*)d_in[3];
    const float* b1    = (const float*)d_in[4];
    const float* W2    = (const float*)d_in[5];
    const float* b2    = (const float*)d_in[6];
    const float* fc1W  = (const float*)d_in[7];
    const float* fc1b  = (const float*)d_in[8];
    const float* fc2W  = (const float*)d_in[9];
    const float* fc2b  = (const float*)d_in[10];
    float* out = (float*)d_out;

    int n = in_sizes[0] / 16;        // 100000
    int E = in_sizes[1] / 2;         // 3200000
    const int* src = ei;
    const int* dst = ei + E;

    const int B = 256;
    int nb = (n + SCAN_B - 1) / SCAN_B;         // 98 <= MAXB

    k_init   <<<(n + B - 1) / B, B>>>(n);
    k_deg    <<<(E + B - 1) / B, B>>>(dst, E);
    k_scan1  <<<nb, SCAN_B>>>(n);
    k_scan2  <<<1, MAXB>>>(nb);
    k_scan3  <<<(n + B - 1) / B, B>>>((const float4*)x, n);
    k_fill   <<<(E + B - 1) / B, B>>>(src, dst, E);
    k_gather1<<<(n + 7) / 8, B>>>(n);
    k_node1  <<<(n + B - 1) / B, B>>>(W1, b1, W2, n);
    k_gather2<<<(n + 7) / 8, B>>>(batch, b2, n);
    k_mlp    <<<(NG + B - 1) / B, B>>>(fc1W, fc1b, fc2W, fc2b, out);
}

// round 5
// speedup vs baseline: 2.2480x; 1.2312x over previous
#include <cuda_runtime.h>
#include <cuda_fp16.h>
#include <cstdint>

// ---------------- problem constants ----------------
#define NN 100000
#define NE 3200000
#define NG 1024
#define SCAN_B 1024
#define MAXB 128              // >= 100000/1024 = 98 scan blocks

// ---------------- scratch ----------------
__device__ int   g_degi[NN];
__device__ int   g_rowstart[NN];
__device__ int   g_rank[NE];
__device__ float g_dinv[NN];
__device__ int   g_blocksum[MAXB];
__device__ int   g_col[NE];                       // CSR: src ids grouped by dst
__device__ __align__(16) __half g_xs [NN * 16];   // x * dinv (fp16), 32B/node
__device__ __align__(16) __half g_t2s[NN * 32];   // (h1@W2) * dinv (fp16), 64B/node
__device__ __align__(16) float  g_agg1[NN * 16];
__device__ float g_gsum[NG * 32];
__device__ float g_gcnt[NG];

// ---------------- helpers ----------------
__device__ __forceinline__ unsigned int h2_bits(float a, float b) {
    __half2 h = __floats2half2_rn(a, b);
    return *reinterpret_cast<unsigned int*>(&h);
}

__device__ __forceinline__ void acc_u4(float* acc, uint4 a) {
    const __half2* h = reinterpret_cast<const __half2*>(&a);
    #pragma unroll
    for (int j = 0; j < 4; j++) {
        float2 f = __half22float2(h[j]);
        acc[2 * j]     += f.x;
        acc[2 * j + 1] += f.y;
    }
}

// butterfly halving: lanes with bit H keep the upper half; feature bit <-> lane bit
template <int H>
__device__ __forceinline__ void halve(float* acc, int lane) {
    bool up = (lane & H) != 0;
    #pragma unroll
    for (int i = 0; i < H; i++) {
        float lo = acc[i], hi = acc[i + H];
        float send = up ? lo : hi;
        float keep = up ? hi : lo;
        acc[i] = keep + __shfl_xor_sync(0xffffffffu, send, H);
    }
}

__device__ __forceinline__ int warp_incl_scan(int v, int lane) {
    #pragma unroll
    for (int d = 1; d < 32; d <<= 1) {
        int x = __shfl_up_sync(0xffffffffu, v, d);
        if (lane >= d) v += x;
    }
    return v;
}

// ---------------- kernels ----------------
__global__ void k_init(int n) {
    int t = blockIdx.x * blockDim.x + threadIdx.x;
    if (t < n) g_degi[t] = 0;
    if (t < NG * 32) g_gsum[t] = 0.f;
    if (t < NG) g_gcnt[t] = 0.f;
}

// degree count + per-edge rank within destination row
__global__ void k_degrank(const int* __restrict__ dst, int E) {
    int e = blockIdx.x * blockDim.x + threadIdx.x;
    if (e < E) g_rank[e] = atomicAdd(&g_degi[dst[e]], 1);
}

// block-level exclusive scan of degrees (warp-shfl based)
__global__ void k_scan1(int n) {
    __shared__ int ws[32];
    int t = threadIdx.x;
    int i = blockIdx.x * SCAN_B + t;
    int lane = t & 31, wid = t >> 5;
    int v = (i < n) ? g_degi[i] : 0;
    int incl = warp_incl_scan(v, lane);
    if (lane == 31) ws[wid] = incl;
    __syncthreads();
    if (wid == 0) {
        int s = ws[lane];
        int si = warp_incl_scan(s, lane);
        ws[lane] = si - s;              // exclusive warp offsets
    }
    __syncthreads();
    int excl = ws[wid] + incl - v;
    if (i < n) g_rowstart[i] = excl;
    if (t == SCAN_B - 1) g_blocksum[blockIdx.x] = excl + v;
}

// finalize rowstart (inline scan of blocksums), dinv, xs = x*dinv (fp16)
__global__ void k_scan3(const float4* __restrict__ x4, int n, int nb) {
    __shared__ int s_off[MAXB];
    int t = threadIdx.x;
    if (t < 32) {
        int vals[4]; int chunk = 0;
        #pragma unroll
        for (int j = 0; j < 4; j++) {
            int idx = t * 4 + j;
            vals[j] = (idx < nb) ? g_blocksum[idx] : 0;
            chunk += vals[j];
        }
        int si = warp_incl_scan(chunk, t);
        int run = si - chunk;
        #pragma unroll
        for (int j = 0; j < 4; j++) { s_off[t * 4 + j] = run; run += vals[j]; }
    }
    __syncthreads();
    int i = blockIdx.x * blockDim.x + t;
    if (i >= n) return;
    g_rowstart[i] += s_off[i >> 10];
    float dv = rsqrtf((float)(g_degi[i] + 1));    // +1 self loop
    g_dinv[i] = dv;
    uint4* o = reinterpret_cast<uint4*>(g_xs + (size_t)i * 16);
    #pragma unroll
    for (int j = 0; j < 2; j++) {
        float4 a = __ldg(x4 + (size_t)i * 4 + 2 * j);
        float4 b = __ldg(x4 + (size_t)i * 4 + 2 * j + 1);
        uint4 u;
        u.x = h2_bits(a.x * dv, a.y * dv);
        u.y = h2_bits(a.z * dv, a.w * dv);
        u.z = h2_bits(b.x * dv, b.y * dv);
        u.w = h2_bits(b.z * dv, b.w * dv);
        o[j] = u;
    }
}

// atomic-free CSR placement using precomputed ranks
__global__ void k_place(const int* __restrict__ src, const int* __restrict__ dst, int E) {
    int e = blockIdx.x * blockDim.x + threadIdx.x;
    if (e >= E) return;
    int pos = g_rowstart[dst[e]] + g_rank[e];
    g_col[pos] = src[e];
}

// Layer-1 gather, 2 lanes per edge (16B each, same 128B line -> 1 wavefront/edge).
// Lanes 0-15 load features 0-7, lanes 16-31 load features 8-15 of edges (lane&15).
__global__ void k_gather1(int n) {
    int w = (blockIdx.x * blockDim.x + threadIdx.x) >> 5;
    int lane = threadIdx.x & 31;
    if (w >= n) return;
    int rs = g_rowstart[w], dg = g_degi[w];
    int h = lane >> 4;                 // half-vector id
    float acc[8];
    #pragma unroll
    for (int i = 0; i < 8; i++) acc[i] = 0.f;
    for (int k = lane & 15; k < dg + 1; k += 16) {      // extra slot = self loop
        int c = (k < dg) ? g_col[rs + k] : w;
        uint4 v = __ldg(reinterpret_cast<const uint4*>(g_xs + (size_t)c * 16) + h);
        acc_u4(acc, v);
    }
    // sum the 16 lanes of each half-group: plain xor8, then halve 4,2,1
    #pragma unroll
    for (int i = 0; i < 8; i++) acc[i] += __shfl_xor_sync(0xffffffffu, acc[i], 8);
    halve<4>(acc, lane); halve<2>(acc, lane); halve<1>(acc, lane);
    // lane holds feature f = h*8 + (lane&7), duplicated across bit3
    if (!(lane & 8))
        g_agg1[(size_t)w * 16 + (h * 8 + (lane & 7))] = acc[0] * g_dinv[w];
}

// Per node MLP: h64 = relu(a16@W1+b1); t2s = (h64@W2)*dinv (fp16).
// Each thread processes TWO nodes to amortize the broadcast-LDS weight reads.
__global__ void k_node1(const float* __restrict__ W1, const float* __restrict__ b1,
                        const float* __restrict__ W2, int n) {
    __shared__ float sW1[16 * 64];
    __shared__ float sb1[64];
    __shared__ float sW2[64 * 32];
    for (int t = threadIdx.x; t < 16 * 64; t += blockDim.x) sW1[t] = W1[t];
    for (int t = threadIdx.x; t < 64;      t += blockDim.x) sb1[t] = b1[t];
    for (int t = threadIdx.x; t < 64 * 32; t += blockDim.x) sW2[t] = W2[t];
    __syncthreads();

    int p = blockIdx.x * blockDim.x + threadIdx.x;
    int i0 = 2 * p;
    if (i0 >= n) return;
    bool two = (i0 + 1 < n);
    int i1 = two ? i0 + 1 : i0;

    float a0[16], a1[16];
    const float4* av0 = reinterpret_cast<const float4*>(g_agg1 + (size_t)i0 * 16);
    const float4* av1 = reinterpret_cast<const float4*>(g_agg1 + (size_t)i1 * 16);
    #pragma unroll
    for (int j = 0; j < 4; j++) {
        float4 v0 = av0[j], v1 = av1[j];
        a0[4*j]=v0.x; a0[4*j+1]=v0.y; a0[4*j+2]=v0.z; a0[4*j+3]=v0.w;
        a1[4*j]=v1.x; a1[4*j+1]=v1.y; a1[4*j+2]=v1.z; a1[4*j+3]=v1.w;
    }

    float t0[32], t1[32];
    #pragma unroll
    for (int k = 0; k < 32; k++) { t0[k] = 0.f; t1[k] = 0.f; }

    #pragma unroll 2
    for (int j = 0; j < 64; j++) {
        float bb = sb1[j];
        float h0 = bb, h1 = bb;
        #pragma unroll
        for (int f = 0; f < 16; f++) {
            float wv = sW1[f * 64 + j];
            h0 += a0[f] * wv;
            h1 += a1[f] * wv;
        }
        h0 = fmaxf(h0, 0.f);
        h1 = fmaxf(h1, 0.f);
        #pragma unroll
        for (int k = 0; k < 32; k++) {
            float wv = sW2[j * 32 + k];
            t0[k] += h0 * wv;
            t1[k] += h1 * wv;
        }
    }

    float dv0 = g_dinv[i0];
    uint4* o0 = reinterpret_cast<uint4*>(g_t2s + (size_t)i0 * 32);
    #pragma unroll
    for (int j = 0; j < 4; j++) {
        uint4 u;
        u.x = h2_bits(t0[8*j]   * dv0, t0[8*j+1] * dv0);
        u.y = h2_bits(t0[8*j+2] * dv0, t0[8*j+3] * dv0);
        u.z = h2_bits(t0[8*j+4] * dv0, t0[8*j+5] * dv0);
        u.w = h2_bits(t0[8*j+6] * dv0, t0[8*j+7] * dv0);
        o0[j] = u;
    }
    if (two) {
        float dv1 = g_dinv[i1];
        uint4* o1 = reinterpret_cast<uint4*>(g_t2s + (size_t)i1 * 32);
        #pragma unroll
        for (int j = 0; j < 4; j++) {
            uint4 u;
            u.x = h2_bits(t1[8*j]   * dv1, t1[8*j+1] * dv1);
            u.y = h2_bits(t1[8*j+2] * dv1, t1[8*j+3] * dv1);
            u.z = h2_bits(t1[8*j+4] * dv1, t1[8*j+5] * dv1);
            u.w = h2_bits(t1[8*j+6] * dv1, t1[8*j+7] * dv1);
            o1[j] = u;
        }
    }
}

// Layer-2 gather, 4 lanes per edge (16B each, same 128B line -> 1 wavefront/edge),
// fused with relu + mean-pool. Quarter q = lane>>3 owns features q*8..q*8+7.
__global__ void k_gather2(const int* __restrict__ batch, const float* __restrict__ b2, int n) {
    int w = (blockIdx.x * blockDim.x + threadIdx.x) >> 5;
    int lane = threadIdx.x & 31;
    if (w >= n) return;
    int rs = g_rowstart[w], dg = g_degi[w];
    int q = lane >> 3;
    float acc[8];
    #pragma unroll
    for (int i = 0; i < 8; i++) acc[i] = 0.f;
    for (int k = lane & 7; k < dg + 1; k += 8) {        // extra slot = self loop
        int c = (k < dg) ? g_col[rs + k] : w;
        uint4 v = __ldg(reinterpret_cast<const uint4*>(g_t2s + (size_t)c * 32) + q);
        acc_u4(acc, v);
    }
    // sum 8 lanes per quarter-group: halve 4,2,1 -> feature f = lane exactly
    halve<4>(acc, lane); halve<2>(acc, lane); halve<1>(acc, lane);
    float h2 = fmaxf(acc[0] * g_dinv[w] + __ldg(b2 + lane), 0.f);
    int b = batch[w];
    atomicAdd(&g_gsum[(size_t)b * 32 + lane], h2);
    if (lane == 0) atomicAdd(&g_gcnt[b], 1.0f);
}

// Per-graph head: mean -> 32x16 relu -> 16x1 sigmoid
__global__ void k_mlp(const float* __restrict__ fc1W, const float* __restrict__ fc1b,
                      const float* __restrict__ fc2W, const float* __restrict__ fc2b,
                      float* __restrict__ out) {
    int t = blockIdx.x * blockDim.x + threadIdx.x;
    if (t >= NG) return;
    float inv = 1.0f / fmaxf(g_gcnt[t], 1.0f);
    float g[32];
    #pragma unroll
    for (int j = 0; j < 32; j++) g[j] = g_gsum[(size_t)t * 32 + j] * inv;
    float r[16];
    #pragma unroll
    for (int j = 0; j < 16; j++) {
        float s = __ldg(fc1b + j);
        #pragma unroll
        for (int i = 0; i < 32; i++) s += g[i] * __ldg(fc1W + i * 16 + j);
        r[j] = fmaxf(s, 0.f);
    }
    float s = __ldg(fc2b);
    #pragma unroll
    for (int j = 0; j < 16; j++) s += r[j] * __ldg(fc2W + j);
    out[t] = 1.0f / (1.0f + expf(-s));
}

// ---------------- launch ----------------
extern "C" void kernel_launch(void* const* d_in, const int* in_sizes, int n_in,
                              void* d_out, int out_size) {
    const float* x     = (const float*)d_in[0];
    const int*   ei    = (const int*)  d_in[1];
    const int*   batch = (const int*)  d_in[2];
    const float* W1    = (const float*)d_in[3];
    const float* b1    = (const float*)d_in[4];
    const float* W2    = (const float*)d_in[5];
    const float* b2    = (const float*)d_in[6];
    const float* fc1W  = (const float*)d_in[7];
    const float* fc1b  = (const float*)d_in[8];
    const float* fc2W  = (const float*)d_in[9];
    const float* fc2b  = (const float*)d_in[10];
    float* out = (float*)d_out;

    int n = in_sizes[0] / 16;        // 100000
    int E = in_sizes[1] / 2;         // 3200000
    const int* src = ei;
    const int* dst = ei + E;

    const int B = 256;
    int nb = (n + SCAN_B - 1) / SCAN_B;         // 98 <= MAXB

    k_init    <<<(n + B - 1) / B, B>>>(n);
    k_degrank <<<(E + B - 1) / B, B>>>(dst, E);
    k_scan1   <<<nb, SCAN_B>>>(n);
    k_scan3   <<<(n + B - 1) / B, B>>>((const float4*)x, n, nb);
    k_place   <<<(E + B - 1) / B, B>>>(src, dst, E);
    k_gather1 <<<(n + 7) / 8, B>>>(n);
    k_node1   <<<(n / 2 + B - 1) / B, B>>>(W1, b1, W2, n);
    k_gather2 <<<(n + 7) / 8, B>>>(batch, b2, n);
    k_mlp     <<<(NG + B - 1) / B, B>>>(fc1W, fc1b, fc2W, fc2b, out);
}